// round 9
// baseline (speedup 1.0000x reference)
#include <cuda_runtime.h>
#include <cuda_fp16.h>
#include <math.h>
#include <stdint.h>

#define T 1024
#define C 128
#define NB 16
#define LUP 523776          // T*(T-1)/2
#define NOUT 2046           // LUP / 256
#define LEAK 0.2f

// ---------------------------------------------------------------------------
// Device globals (scratch)
// ---------------------------------------------------------------------------
__device__ __half g_up[(size_t)NB * LUP];  // packed upper-triangle distances (fp16)
__device__ float g_xx[NB * T];             // row squared norms

// ---------------------------------------------------------------------------
// Helpers
// ---------------------------------------------------------------------------
__device__ __forceinline__ uint32_t to_tf32(float f) {
    uint32_t r;
    asm("cvt.rna.tf32.f32 %0, %1;" : "=r"(r) : "f"(f));
    return r;
}

__device__ __forceinline__ void mma_tf32(float* d, const uint32_t* a, const uint32_t* b) {
    asm volatile(
        "mma.sync.aligned.m16n8k8.row.col.f32.tf32.tf32.f32 "
        "{%0,%1,%2,%3}, {%4,%5,%6,%7}, {%8,%9}, {%0,%1,%2,%3};"
        : "+f"(d[0]), "+f"(d[1]), "+f"(d[2]), "+f"(d[3])
        : "r"(a[0]), "r"(a[1]), "r"(a[2]), "r"(a[3]),
          "r"(b[0]), "r"(b[1]));
}

__device__ __forceinline__ float lrelu(float v) {
    return fmaxf(v, LEAK * v);
}

__device__ __forceinline__ float fsqrt_approx(float v) {
    float r;
    asm("sqrt.approx.f32 %0, %1;" : "=f"(r) : "f"(v));
    return r;
}

// ---------------------------------------------------------------------------
// Kernel 1: xx[b][i] = sum_c x[b][i][c]^2.  One warp per row.
// ---------------------------------------------------------------------------
__global__ __launch_bounds__(256) void xx_kernel(const float* __restrict__ x) {
    int warp = (blockIdx.x * 256 + threadIdx.x) >> 5;
    int lane = threadIdx.x & 31;
    if (warp >= NB * T) return;
    const float4* row = (const float4*)(x + (size_t)warp * C);
    float4 v = row[lane];
    float s = v.x * v.x + v.y * v.y + v.z * v.z + v.w * v.w;
    #pragma unroll
    for (int o = 16; o; o >>= 1) s += __shfl_xor_sync(0xffffffffu, s, o);
    if (lane == 0) g_xx[warp] = s;
}

// ---------------------------------------------------------------------------
// Kernel 2: tf32 mma.sync Gram tiles -> packed fp16 sqrt distances.
// (verbatim from the 151.8us round-8 build)
// ---------------------------------------------------------------------------
#define AS_STRIDE 132
#define AS_BYTES  (128 * AS_STRIDE * 4)       // 67584
#define DIST_SMEM (2 * AS_BYTES)              // 135168
#define HS_STRIDE 130                          // half staging stride (even)

__global__ __launch_bounds__(256) void dist_kernel(const float* __restrict__ x) {
    extern __shared__ __align__(16) unsigned char sm[];
    uint32_t* As = (uint32_t*)sm;
    uint32_t* Bs = (uint32_t*)(sm + AS_BYTES);

    int tid = threadIdx.x;
    int wid = tid >> 5;
    int lane = tid & 31;
    int grp = lane >> 2;        // 0..7
    int tg  = lane & 3;         // 0..3

    int b = blockIdx.y;
    int t = blockIdx.x;
    int ti = 0, rem = t;
    while (rem >= 8 - ti) { rem -= 8 - ti; ++ti; }
    int tj = ti + rem;
    int i0 = ti * 128, j0 = tj * 128;

    const float* xb = x + (size_t)b * T * C;

    #pragma unroll
    for (int it = 0; it < 16; ++it) {
        int f4 = it * 256 + tid;
        int row = f4 >> 5, c4 = f4 & 31;
        float4 va = *(const float4*)(xb + (size_t)(i0 + row) * C + c4 * 4);
        uint4 ta = make_uint4(to_tf32(va.x), to_tf32(va.y), to_tf32(va.z), to_tf32(va.w));
        *(uint4*)&As[row * AS_STRIDE + c4 * 4] = ta;
        float4 vb = *(const float4*)(xb + (size_t)(j0 + row) * C + c4 * 4);
        uint4 tb = make_uint4(to_tf32(vb.x), to_tf32(vb.y), to_tf32(vb.z), to_tf32(vb.w));
        *(uint4*)&Bs[row * AS_STRIDE + c4 * 4] = tb;
    }
    __syncthreads();

    int warp_m = (wid >> 2) * 64;
    int warp_n = (wid & 3) * 32;

    float acc[4][4][4];
    #pragma unroll
    for (int e = 0; e < 4; ++e)
        #pragma unroll
        for (int f = 0; f < 4; ++f)
            #pragma unroll
            for (int q = 0; q < 4; ++q) acc[e][f][q] = 0.0f;

    int abase = (warp_m + grp) * AS_STRIDE + tg;
    int bbase = (warp_n + grp) * AS_STRIDE + tg;

    #pragma unroll 2
    for (int kb = 0; kb < 128; kb += 8) {
        uint32_t a[4][4], bf[4][2];
        #pragma unroll
        for (int e = 0; e < 4; ++e) {
            int r = abase + 16 * e * AS_STRIDE + kb;
            a[e][0] = As[r];
            a[e][1] = As[r + 8 * AS_STRIDE];
            a[e][2] = As[r + 4];
            a[e][3] = As[r + 8 * AS_STRIDE + 4];
        }
        #pragma unroll
        for (int f = 0; f < 4; ++f) {
            int r = bbase + 8 * f * AS_STRIDE + kb;
            bf[f][0] = Bs[r];
            bf[f][1] = Bs[r + 4];
        }
        #pragma unroll
        for (int e = 0; e < 4; ++e)
            #pragma unroll
            for (int f = 0; f < 4; ++f)
                mma_tf32(acc[e][f], a[e], bf[f]);
    }

    float xi[4][2], xj[4][2];
    #pragma unroll
    for (int e = 0; e < 4; ++e) {
        int il = warp_m + 16 * e + grp;
        xi[e][0] = g_xx[b * T + i0 + il];
        xi[e][1] = g_xx[b * T + i0 + il + 8];
    }
    #pragma unroll
    for (int f = 0; f < 4; ++f) {
        int jl = warp_n + 8 * f + 2 * tg;
        xj[f][0] = g_xx[b * T + j0 + jl];
        xj[f][1] = g_xx[b * T + j0 + jl + 1];
    }

    __syncthreads();
    __half* S = (__half*)sm;   // 128 x stride-130 half staging

    #pragma unroll
    for (int e = 0; e < 4; ++e) {
        int il = warp_m + 16 * e + grp;
        #pragma unroll
        for (int f = 0; f < 4; ++f) {
            int jl = warp_n + 8 * f + 2 * tg;   // even
            float d00 = fmaf(-2.0f, acc[e][f][0], xi[e][0] + xj[f][0]);
            float d01 = fmaf(-2.0f, acc[e][f][1], xi[e][0] + xj[f][1]);
            float d10 = fmaf(-2.0f, acc[e][f][2], xi[e][1] + xj[f][0]);
            float d11 = fmaf(-2.0f, acc[e][f][3], xi[e][1] + xj[f][1]);
            float s00 = fsqrt_approx(fmaxf(d00, 0.0f));
            float s01 = fsqrt_approx(fmaxf(d01, 0.0f));
            float s10 = fsqrt_approx(fmaxf(d10, 0.0f));
            float s11 = fsqrt_approx(fmaxf(d11, 0.0f));
            *(__half2*)&S[il * HS_STRIDE + jl]       = __floats2half2_rn(s00, s01);
            *(__half2*)&S[(il + 8) * HS_STRIDE + jl] = __floats2half2_rn(s10, s11);
        }
    }
    __syncthreads();

    {
        long bbase2 = (long)b * LUP;
        #pragma unroll
        for (int q = tid; q < 128 * 128; q += 256) {
            int m = q >> 7, jj = q & 127;
            int i2 = i0 + m, j2 = j0 + jj;
            if (j2 > i2) {
                long ro = (long)i2 * (2 * T - 1 - i2) / 2 - i2 - 1;
                g_up[bbase2 + ro + j2] = S[m * HS_STRIDE + jj];
            }
        }
    }
}

// ---------------------------------------------------------------------------
// Kernel 3 (v5): conv with XOR-swizzled activation buffers.
// Layout: word(p,c) = 8p + ((c>>2 ^ sig(p))<<2) + (c&3), sig(p) = (p>>2)&1.
//  - STS (stride-8 writer): conflict-free (unchanged property).
//  - LDS.128 reader of positions (2p, 2p+1): the swizzle spreads the 4 lane
//    groups over 4 disjoint bank quads per instruction (was 2-way conflicted).
// Reader swaps chunk pairs when sig(2p)=1 (sig(2p)==sig(2p+1) always).
// ---------------------------------------------------------------------------
#define SIG(p) (((p) >> 2) & 1)

__global__ __launch_bounds__(256) void conv_kernel(
    const float* __restrict__ w0, const float* __restrict__ b0,
    const float* __restrict__ w1, const float* __restrict__ b1,
    const float* __restrict__ w2, const float* __restrict__ b2,
    const float* __restrict__ w3, const float* __restrict__ b3,
    const float* __restrict__ w4, const float* __restrict__ b4,
    const float* __restrict__ w5, const float* __restrict__ b5,
    const float* __restrict__ w6, const float* __restrict__ b6,
    const float* __restrict__ w7, const float* __restrict__ b7,
    float* __restrict__ out)
{
    __shared__ float A[6144];       // 8ch x 768, swizzled channel-inner
    __shared__ float Bu[3072];      // ping-pong buffer (swizzled)
    __shared__ __half BuH[1536];    // fp16 input staging
    __shared__ float wgt[860];

    int tid = threadIdx.x;
    int c   = tid & 7;
    int j   = c >> 2;               // chunk bit of this thread's channel
    int cl  = c & 3;
    int b   = blockIdx.y;
    int blk = blockIdx.x;        // 0..340

    // ---- stage weights ----
    if (tid < 128) {
        wgt[ 24 + tid] = w1[tid];
        wgt[152 + tid] = w2[tid];
        wgt[280 + tid] = w3[tid];
        wgt[408 + tid] = w4[tid];
        wgt[536 + tid] = w5[tid];
        wgt[664 + tid] = w6[tid];
    } else {
        int u = tid - 128;
        if (u < 16)       wgt[u]            = w0[u];
        else if (u < 24)  wgt[u]            = b0[u - 16];
        else if (u < 32)  wgt[792 + (u-24)] = b1[u-24];
        else if (u < 40)  wgt[800 + (u-32)] = b2[u-32];
        else if (u < 48)  wgt[808 + (u-40)] = b3[u-40];
        else if (u < 56)  wgt[816 + (u-48)] = b4[u-48];
        else if (u < 64)  wgt[824 + (u-56)] = b5[u-56];
        else if (u < 72)  wgt[832 + (u-64)] = b6[u-64];
        else if (u < 88)  wgt[840 + (u-72)] = w7[u-72];
        else if (u == 88) wgt[856]          = b7[0];
    }

    // ---- load 1536 contiguous fp16 distances (3KB, uint4) ----
    {
        const uint4* src = (const uint4*)(g_up + (size_t)b * LUP + (size_t)blk * 1536);
        uint4* dst = (uint4*)BuH;
        if (tid < 192) dst[tid] = src[tid];
    }
    __syncthreads();

    // ---- layer 0: 1ch x 1536 -> 8ch x 768 (half2 broadcast in, swizzled out) ----
    {
        float wa = wgt[2 * c], wb2 = wgt[2 * c + 1], bc = wgt[16 + c];
        const __half2* B2 = (const __half2*)BuH;
        #pragma unroll
        for (int it = 0; it < 24; ++it) {
            int q = it * 256 + tid;          // 0..6143
            int p = q >> 3;                  // (q&7)==c
            float2 u = __half22float2(B2[p]);
            float v = fmaf(wa, u.x, fmaf(wb2, u.y, bc));
            A[8 * p + ((j ^ SIG(p)) << 2) + cl] = lrelu(v);
        }
    }
    __syncthreads();

    // ---- layers 1..6: 8ch -> 8ch, halving (register weights, swizzled LDS.128) ----
    float* src = A;
    float* dst = Bu;
    int len = 768;
    #pragma unroll 1
    for (int l = 0; l < 6; ++l) {
        int olen = len >> 1;
        const float4* Wc = (const float4*)(wgt + 24 + l * 128 + c * 16);
        float4 wrA = Wc[0], wrB = Wc[1], wrC = Wc[2], wrD = Wc[3];
        float bc = wgt[792 + l * 8 + c];

        for (int q = tid; q < 8 * olen; q += 256) {
            int p = q >> 3;                  // output position; (q&7)==c
            const float4* s4 = (const float4*)(src + 16 * p);
            float4 u0 = s4[0], u1 = s4[1], u2 = s4[2], u3 = s4[3];
            int sr = SIG(2 * p);             // == SIG(2p+1)
            // de-swizzle: chunk pair swap when sr==1
            float4 a0 = sr ? u1 : u0;
            float4 a1 = sr ? u0 : u1;
            float4 a2 = sr ? u3 : u2;
            float4 a3 = sr ? u2 : u3;
            float acc = bc;
            acc = fmaf(wrA.x, a0.x, acc); acc = fmaf(wrA.y, a2.x, acc);
            acc = fmaf(wrA.z, a0.y, acc); acc = fmaf(wrA.w, a2.y, acc);
            acc = fmaf(wrB.x, a0.z, acc); acc = fmaf(wrB.y, a2.z, acc);
            acc = fmaf(wrB.z, a0.w, acc); acc = fmaf(wrB.w, a2.w, acc);
            acc = fmaf(wrC.x, a1.x, acc); acc = fmaf(wrC.y, a3.x, acc);
            acc = fmaf(wrC.z, a1.y, acc); acc = fmaf(wrC.w, a3.y, acc);
            acc = fmaf(wrD.x, a1.z, acc); acc = fmaf(wrD.y, a3.z, acc);
            acc = fmaf(wrD.z, a1.w, acc); acc = fmaf(wrD.w, a3.w, acc);
            dst[8 * p + ((j ^ SIG(p)) << 2) + cl] = lrelu(acc);
        }
        __syncthreads();
        float* tmp = src; src = dst; dst = tmp;
        len = olen;
    }

    // ---- layer 7: 8ch x 12 -> 1ch x 6 (swizzle-aware scalar reads) ----
    if (tid < 6) {
        int p0 = 2 * tid, p1 = 2 * tid + 1;
        int s0w = SIG(p0) << 2;              // == SIG(p1) << 2
        const float* r0 = src + 8 * p0;
        const float* r1 = src + 8 * p1;
        const float4* Wc = (const float4*)(wgt + 840);
        float4 wa = Wc[0], wb = Wc[1], wc2 = Wc[2], wd = Wc[3];
        // channel ci at position p: word 8p + (((ci>>2)^sig)<<2) + (ci&3)
        float acc = wgt[856];
        acc = fmaf(wa.x,  r0[(0 ^ s0w) + 0], acc); acc = fmaf(wa.y,  r1[(0 ^ s0w) + 0], acc);
        acc = fmaf(wa.z,  r0[(0 ^ s0w) + 1], acc); acc = fmaf(wa.w,  r1[(0 ^ s0w) + 1], acc);
        acc = fmaf(wb.x,  r0[(0 ^ s0w) + 2], acc); acc = fmaf(wb.y,  r1[(0 ^ s0w) + 2], acc);
        acc = fmaf(wb.z,  r0[(0 ^ s0w) + 3], acc); acc = fmaf(wb.w,  r1[(0 ^ s0w) + 3], acc);
        acc = fmaf(wc2.x, r0[(4 ^ s0w) + 0], acc); acc = fmaf(wc2.y, r1[(4 ^ s0w) + 0], acc);
        acc = fmaf(wc2.z, r0[(4 ^ s0w) + 1], acc); acc = fmaf(wc2.w, r1[(4 ^ s0w) + 1], acc);
        acc = fmaf(wd.x,  r0[(4 ^ s0w) + 2], acc); acc = fmaf(wd.y,  r1[(4 ^ s0w) + 2], acc);
        acc = fmaf(wd.z,  r0[(4 ^ s0w) + 3], acc); acc = fmaf(wd.w,  r1[(4 ^ s0w) + 3], acc);
        out[b * NOUT + blk * 6 + tid] = acc;
    }
}

// ---------------------------------------------------------------------------
extern "C" void kernel_launch(void* const* d_in, const int* in_sizes, int n_in,
                              void* d_out, int out_size) {
    const float* x = (const float*)d_in[0];
    const float* w[8];
    const float* bb[8];
    for (int i = 0; i < 8; ++i) {
        w[i]  = (const float*)d_in[1 + 2 * i];
        bb[i] = (const float*)d_in[2 + 2 * i];
    }
    float* out = (float*)d_out;

    cudaFuncSetAttribute(dist_kernel,
                         cudaFuncAttributeMaxDynamicSharedMemorySize, DIST_SMEM);

    xx_kernel<<<(NB * T) / 8, 256>>>(x);
    dist_kernel<<<dim3(36, NB), 256, DIST_SMEM>>>(x);
    conv_kernel<<<dim3(341, NB), 256>>>(
        w[0], bb[0], w[1], bb[1], w[2], bb[2], w[3], bb[3],
        w[4], bb[4], w[5], bb[5], w[6], bb[6], w[7], bb[7], out);
}

// round 10
// speedup vs baseline: 1.1204x; 1.1204x over previous
#include <cuda_runtime.h>
#include <cuda_fp16.h>
#include <math.h>
#include <stdint.h>

#define T 1024
#define C 128
#define NB 16
#define LUP 523776          // T*(T-1)/2
#define NOUT 2046           // LUP / 256
#define LEAK 0.2f

// ---------------------------------------------------------------------------
// Device globals (scratch)
// ---------------------------------------------------------------------------
__device__ __half g_up[(size_t)NB * LUP];  // packed upper-triangle distances (fp16)

// ---------------------------------------------------------------------------
// Helpers
// ---------------------------------------------------------------------------
__device__ __forceinline__ uint32_t to_tf32(float f) {
    uint32_t r;
    asm("cvt.rna.tf32.f32 %0, %1;" : "=r"(r) : "f"(f));
    return r;
}

__device__ __forceinline__ void mma_tf32(float* d, const uint32_t* a, const uint32_t* b) {
    asm volatile(
        "mma.sync.aligned.m16n8k8.row.col.f32.tf32.tf32.f32 "
        "{%0,%1,%2,%3}, {%4,%5,%6,%7}, {%8,%9}, {%0,%1,%2,%3};"
        : "+f"(d[0]), "+f"(d[1]), "+f"(d[2]), "+f"(d[3])
        : "r"(a[0]), "r"(a[1]), "r"(a[2]), "r"(a[3]),
          "r"(b[0]), "r"(b[1]));
}

__device__ __forceinline__ float lrelu(float v) {
    return fmaxf(v, LEAK * v);
}

__device__ __forceinline__ float fsqrt_approx(float v) {
    float r;
    asm("sqrt.approx.f32 %0, %1;" : "=f"(r) : "f"(v));
    return r;
}

// ---------------------------------------------------------------------------
// Kernel 1: tf32 mma.sync Gram tiles -> packed fp16 sqrt distances.
// Row squared-norms are computed IN-BLOCK from the tf32 tiles (xx_kernel
// eliminated). sxx[0..127] = A rows, sxx[128..255] = B rows.
// ---------------------------------------------------------------------------
#define AS_STRIDE 132
#define AS_BYTES  (128 * AS_STRIDE * 4)       // 67584
#define DIST_SMEM (2 * AS_BYTES + 1024)       // + sxx[256]
#define HS_STRIDE 130                          // half staging stride (even)

__global__ __launch_bounds__(256) void dist_kernel(const float* __restrict__ x) {
    extern __shared__ __align__(16) unsigned char sm[];
    uint32_t* As = (uint32_t*)sm;
    uint32_t* Bs = (uint32_t*)(sm + AS_BYTES);
    float* sxx   = (float*)(sm + 2 * AS_BYTES);

    int tid = threadIdx.x;
    int wid = tid >> 5;
    int lane = tid & 31;
    int grp = lane >> 2;        // 0..7
    int tg  = lane & 3;         // 0..3

    int b = blockIdx.y;
    int t = blockIdx.x;
    int ti = 0, rem = t;
    while (rem >= 8 - ti) { rem -= 8 - ti; ++ti; }
    int tj = ti + rem;
    int i0 = ti * 128, j0 = tj * 128;

    const float* xb = x + (size_t)b * T * C;

    #pragma unroll
    for (int it = 0; it < 16; ++it) {
        int f4 = it * 256 + tid;
        int row = f4 >> 5, c4 = f4 & 31;
        float4 va = *(const float4*)(xb + (size_t)(i0 + row) * C + c4 * 4);
        uint4 ta = make_uint4(to_tf32(va.x), to_tf32(va.y), to_tf32(va.z), to_tf32(va.w));
        *(uint4*)&As[row * AS_STRIDE + c4 * 4] = ta;
        float4 vb = *(const float4*)(xb + (size_t)(j0 + row) * C + c4 * 4);
        uint4 tb = make_uint4(to_tf32(vb.x), to_tf32(vb.y), to_tf32(vb.z), to_tf32(vb.w));
        *(uint4*)&Bs[row * AS_STRIDE + c4 * 4] = tb;
    }
    __syncthreads();

    // ---- in-block row squared norms from the tf32 tiles ----
    {
        int r = tid & 127;
        const uint32_t* Row = ((tid < 128) ? As : Bs) + r * AS_STRIDE;
        float s = 0.0f;
        #pragma unroll
        for (int k = 0; k < 128; k += 4) {
            float4 v = *(const float4*)&Row[k];
            s = fmaf(v.x, v.x, s); s = fmaf(v.y, v.y, s);
            s = fmaf(v.z, v.z, s); s = fmaf(v.w, v.w, s);
        }
        sxx[tid] = s;            // ordered for readers by the post-mainloop barrier
    }

    int warp_m = (wid >> 2) * 64;
    int warp_n = (wid & 3) * 32;

    float acc[4][4][4];
    #pragma unroll
    for (int e = 0; e < 4; ++e)
        #pragma unroll
        for (int f = 0; f < 4; ++f)
            #pragma unroll
            for (int q = 0; q < 4; ++q) acc[e][f][q] = 0.0f;

    int abase = (warp_m + grp) * AS_STRIDE + tg;
    int bbase = (warp_n + grp) * AS_STRIDE + tg;

    #pragma unroll 2
    for (int kb = 0; kb < 128; kb += 8) {
        uint32_t a[4][4], bf[4][2];
        #pragma unroll
        for (int e = 0; e < 4; ++e) {
            int r = abase + 16 * e * AS_STRIDE + kb;
            a[e][0] = As[r];
            a[e][1] = As[r + 8 * AS_STRIDE];
            a[e][2] = As[r + 4];
            a[e][3] = As[r + 8 * AS_STRIDE + 4];
        }
        #pragma unroll
        for (int f = 0; f < 4; ++f) {
            int r = bbase + 8 * f * AS_STRIDE + kb;
            bf[f][0] = Bs[r];
            bf[f][1] = Bs[r + 4];
        }
        #pragma unroll
        for (int e = 0; e < 4; ++e)
            #pragma unroll
            for (int f = 0; f < 4; ++f)
                mma_tf32(acc[e][f], a[e], bf[f]);
    }

    // barrier: orders sxx writes before reads, and As/Bs reads before staging reuse
    __syncthreads();

    float xi[4][2], xj[4][2];
    #pragma unroll
    for (int e = 0; e < 4; ++e) {
        int il = warp_m + 16 * e + grp;
        xi[e][0] = sxx[il];
        xi[e][1] = sxx[il + 8];
    }
    #pragma unroll
    for (int f = 0; f < 4; ++f) {
        int jl = warp_n + 8 * f + 2 * tg;
        xj[f][0] = sxx[128 + jl];
        xj[f][1] = sxx[128 + jl + 1];
    }

    __half* S = (__half*)sm;   // 128 x stride-130 half staging (reuses As region)

    #pragma unroll
    for (int e = 0; e < 4; ++e) {
        int il = warp_m + 16 * e + grp;
        #pragma unroll
        for (int f = 0; f < 4; ++f) {
            int jl = warp_n + 8 * f + 2 * tg;   // even
            float d00 = fmaf(-2.0f, acc[e][f][0], xi[e][0] + xj[f][0]);
            float d01 = fmaf(-2.0f, acc[e][f][1], xi[e][0] + xj[f][1]);
            float d10 = fmaf(-2.0f, acc[e][f][2], xi[e][1] + xj[f][0]);
            float d11 = fmaf(-2.0f, acc[e][f][3], xi[e][1] + xj[f][1]);
            float s00 = fsqrt_approx(fmaxf(d00, 0.0f));
            float s01 = fsqrt_approx(fmaxf(d01, 0.0f));
            float s10 = fsqrt_approx(fmaxf(d10, 0.0f));
            float s11 = fsqrt_approx(fmaxf(d11, 0.0f));
            *(__half2*)&S[il * HS_STRIDE + jl]       = __floats2half2_rn(s00, s01);
            *(__half2*)&S[(il + 8) * HS_STRIDE + jl] = __floats2half2_rn(s10, s11);
        }
    }
    __syncthreads();

    {
        long bbase2 = (long)b * LUP;
        #pragma unroll
        for (int q = tid; q < 128 * 128; q += 256) {
            int m = q >> 7, jj = q & 127;
            int i2 = i0 + m, j2 = j0 + jj;
            if (j2 > i2) {
                long ro = (long)i2 * (2 * T - 1 - i2) / 2 - i2 - 1;
                g_up[bbase2 + ro + j2] = S[m * HS_STRIDE + jj];
            }
        }
    }
}

// ---------------------------------------------------------------------------
// Kernel 2: conv stack — verbatim from the 151.8us round-8 build.
// ---------------------------------------------------------------------------
__global__ __launch_bounds__(256) void conv_kernel(
    const float* __restrict__ w0, const float* __restrict__ b0,
    const float* __restrict__ w1, const float* __restrict__ b1,
    const float* __restrict__ w2, const float* __restrict__ b2,
    const float* __restrict__ w3, const float* __restrict__ b3,
    const float* __restrict__ w4, const float* __restrict__ b4,
    const float* __restrict__ w5, const float* __restrict__ b5,
    const float* __restrict__ w6, const float* __restrict__ b6,
    const float* __restrict__ w7, const float* __restrict__ b7,
    float* __restrict__ out)
{
    __shared__ float A[6144];       // 8ch x 768, channel-inner
    __shared__ float Bu[3072];      // ping-pong buffer
    __shared__ __half BuH[1536];    // fp16 input staging
    __shared__ float wgt[860];

    int tid = threadIdx.x;
    int c   = tid & 7;
    int b   = blockIdx.y;
    int blk = blockIdx.x;        // 0..340

    // ---- stage weights ----
    if (tid < 128) {
        wgt[ 24 + tid] = w1[tid];
        wgt[152 + tid] = w2[tid];
        wgt[280 + tid] = w3[tid];
        wgt[408 + tid] = w4[tid];
        wgt[536 + tid] = w5[tid];
        wgt[664 + tid] = w6[tid];
    } else {
        int u = tid - 128;
        if (u < 16)       wgt[u]            = w0[u];
        else if (u < 24)  wgt[u]            = b0[u - 16];
        else if (u < 32)  wgt[792 + (u-24)] = b1[u-24];
        else if (u < 40)  wgt[800 + (u-32)] = b2[u-32];
        else if (u < 48)  wgt[808 + (u-40)] = b3[u-40];
        else if (u < 56)  wgt[816 + (u-48)] = b4[u-48];
        else if (u < 64)  wgt[824 + (u-56)] = b5[u-56];
        else if (u < 72)  wgt[832 + (u-64)] = b6[u-64];
        else if (u < 88)  wgt[840 + (u-72)] = w7[u-72];
        else if (u == 88) wgt[856]          = b7[0];
    }

    // ---- load 1536 contiguous fp16 distances (3KB, uint4) ----
    {
        const uint4* src = (const uint4*)(g_up + (size_t)b * LUP + (size_t)blk * 1536);
        uint4* dst = (uint4*)BuH;
        if (tid < 192) dst[tid] = src[tid];
    }
    __syncthreads();

    // ---- layer 0: 1ch x 1536 -> 8ch x 768 (half2 broadcast in) ----
    {
        float wa = wgt[2 * c], wb2 = wgt[2 * c + 1], bc = wgt[16 + c];
        const __half2* B2 = (const __half2*)BuH;
        #pragma unroll
        for (int it = 0; it < 24; ++it) {
            int q = it * 256 + tid;          // 0..6143
            int p = q >> 3;                  // (q&7)==c
            float2 u = __half22float2(B2[p]);
            float v = fmaf(wa, u.x, fmaf(wb2, u.y, bc));
            A[p * 8 + c] = lrelu(v);
        }
    }
    __syncthreads();

    // ---- layers 1..6: 8ch -> 8ch, halving (register weights, LDS.128 in) ----
    float* src = A;
    float* dst = Bu;
    int len = 768;
    #pragma unroll 1
    for (int l = 0; l < 6; ++l) {
        int olen = len >> 1;
        const float4* Wc = (const float4*)(wgt + 24 + l * 128 + c * 16);
        float4 wrA = Wc[0], wrB = Wc[1], wrC = Wc[2], wrD = Wc[3];
        float bc = wgt[792 + l * 8 + c];

        for (int q = tid; q < 8 * olen; q += 256) {
            int p = q >> 3;                  // (q&7)==c
            const float4* s4 = (const float4*)(src + 16 * p);
            float4 a0 = s4[0], a1 = s4[1], a2 = s4[2], a3 = s4[3];
            float acc = bc;
            acc = fmaf(wrA.x, a0.x, acc); acc = fmaf(wrA.y, a2.x, acc);
            acc = fmaf(wrA.z, a0.y, acc); acc = fmaf(wrA.w, a2.y, acc);
            acc = fmaf(wrB.x, a0.z, acc); acc = fmaf(wrB.y, a2.z, acc);
            acc = fmaf(wrB.z, a0.w, acc); acc = fmaf(wrB.w, a2.w, acc);
            acc = fmaf(wrC.x, a1.x, acc); acc = fmaf(wrC.y, a3.x, acc);
            acc = fmaf(wrC.z, a1.y, acc); acc = fmaf(wrC.w, a3.y, acc);
            acc = fmaf(wrD.x, a1.z, acc); acc = fmaf(wrD.y, a3.z, acc);
            acc = fmaf(wrD.z, a1.w, acc); acc = fmaf(wrD.w, a3.w, acc);
            dst[p * 8 + c] = lrelu(acc);
        }
        __syncthreads();
        float* tmp = src; src = dst; dst = tmp;
        len = olen;
    }

    // ---- layer 7: 8ch x 12 -> 1ch x 6 (no activation) ----
    if (tid < 6) {
        const float* s0 = src + 16 * tid;
        const float4* Wc = (const float4*)(wgt + 840);
        float4 wa = Wc[0], wb = Wc[1], wc2 = Wc[2], wd = Wc[3];
        float acc = wgt[856];
        acc = fmaf(wa.x,  s0[0], acc); acc = fmaf(wa.y,  s0[8],  acc);
        acc = fmaf(wa.z,  s0[1], acc); acc = fmaf(wa.w,  s0[9],  acc);
        acc = fmaf(wb.x,  s0[2], acc); acc = fmaf(wb.y,  s0[10], acc);
        acc = fmaf(wb.z,  s0[3], acc); acc = fmaf(wb.w,  s0[11], acc);
        acc = fmaf(wc2.x, s0[4], acc); acc = fmaf(wc2.y, s0[12], acc);
        acc = fmaf(wc2.z, s0[5], acc); acc = fmaf(wc2.w, s0[13], acc);
        acc = fmaf(wd.x,  s0[6], acc); acc = fmaf(wd.y,  s0[14], acc);
        acc = fmaf(wd.z,  s0[7], acc); acc = fmaf(wd.w,  s0[15], acc);
        out[b * NOUT + blk * 6 + tid] = acc;
    }
}

// ---------------------------------------------------------------------------
extern "C" void kernel_launch(void* const* d_in, const int* in_sizes, int n_in,
                              void* d_out, int out_size) {
    const float* x = (const float*)d_in[0];
    const float* w[8];
    const float* bb[8];
    for (int i = 0; i < 8; ++i) {
        w[i]  = (const float*)d_in[1 + 2 * i];
        bb[i] = (const float*)d_in[2 + 2 * i];
    }
    float* out = (float*)d_out;

    cudaFuncSetAttribute(dist_kernel,
                         cudaFuncAttributeMaxDynamicSharedMemorySize, DIST_SMEM);

    dist_kernel<<<dim3(36, NB), 256, DIST_SMEM>>>(x);
    conv_kernel<<<dim3(341, NB), 256>>>(
        w[0], bb[0], w[1], bb[1], w[2], bb[2], w[3], bb[3],
        w[4], bb[4], w[5], bb[5], w[6], bb[6], w[7], bb[7], out);
}

// round 12
// speedup vs baseline: 1.6400x; 1.4637x over previous
#include <cuda_runtime.h>
#include <cuda_fp16.h>
#include <math.h>
#include <stdint.h>

#define T 1024
#define C 128
#define NB 16
#define LUP 523776          // T*(T-1)/2
#define NOUT 2046           // LUP / 256
#define LEAK 0.2f

// ---------------------------------------------------------------------------
// Device globals (scratch)
// ---------------------------------------------------------------------------
__device__ __half g_up[(size_t)NB * LUP];  // packed upper-triangle distances (fp16)

// ---------------------------------------------------------------------------
// Helpers
// ---------------------------------------------------------------------------
__device__ __forceinline__ uint32_t to_tf32(float f) {
    uint32_t r;
    asm("cvt.rna.tf32.f32 %0, %1;" : "=r"(r) : "f"(f));
    return r;
}

__device__ __forceinline__ void mma_tf32(float* d, const uint32_t* a, const uint32_t* b) {
    asm volatile(
        "mma.sync.aligned.m16n8k8.row.col.f32.tf32.tf32.f32 "
        "{%0,%1,%2,%3}, {%4,%5,%6,%7}, {%8,%9}, {%0,%1,%2,%3};"
        : "+f"(d[0]), "+f"(d[1]), "+f"(d[2]), "+f"(d[3])
        : "r"(a[0]), "r"(a[1]), "r"(a[2]), "r"(a[3]),
          "r"(b[0]), "r"(b[1]));
}

__device__ __forceinline__ void mma_f16(float* d, const uint32_t* a, const uint32_t* b) {
    asm volatile(
        "mma.sync.aligned.m16n8k16.row.col.f32.f16.f16.f32 "
        "{%0,%1,%2,%3}, {%4,%5,%6,%7}, {%8,%9}, {%0,%1,%2,%3};"
        : "+f"(d[0]), "+f"(d[1]), "+f"(d[2]), "+f"(d[3])
        : "r"(a[0]), "r"(a[1]), "r"(a[2]), "r"(a[3]),
          "r"(b[0]), "r"(b[1]));
}

__device__ __forceinline__ float lrelu(float v) {
    return fmaxf(v, LEAK * v);
}

__device__ __forceinline__ float fsqrt_approx(float v) {
    float r;
    asm("sqrt.approx.f32 %0, %1;" : "=f"(r) : "f"(v));
    return r;
}

__device__ __forceinline__ uint32_t pack_h2(float x, float y) {
    __half2 h = __floats2half2_rn(x, y);
    return *(uint32_t*)&h;
}

// ---------------------------------------------------------------------------
// Kernel 1: tf32 mma.sync Gram tiles -> packed fp16 sqrt distances.
// (verbatim from round-10 passing build; xx fused in-block)
// ---------------------------------------------------------------------------
#define AS_STRIDE 132
#define AS_BYTES  (128 * AS_STRIDE * 4)       // 67584
#define DIST_SMEM (2 * AS_BYTES + 1024)       // + sxx[256]
#define HS_STRIDE 130

__global__ __launch_bounds__(256) void dist_kernel(const float* __restrict__ x) {
    extern __shared__ __align__(16) unsigned char sm[];
    uint32_t* As = (uint32_t*)sm;
    uint32_t* Bs = (uint32_t*)(sm + AS_BYTES);
    float* sxx   = (float*)(sm + 2 * AS_BYTES);

    int tid = threadIdx.x;
    int wid = tid >> 5;
    int lane = tid & 31;
    int grp = lane >> 2;
    int tg  = lane & 3;

    int b = blockIdx.y;
    int t = blockIdx.x;
    int ti = 0, rem = t;
    while (rem >= 8 - ti) { rem -= 8 - ti; ++ti; }
    int tj = ti + rem;
    int i0 = ti * 128, j0 = tj * 128;

    const float* xb = x + (size_t)b * T * C;

    #pragma unroll
    for (int it = 0; it < 16; ++it) {
        int f4 = it * 256 + tid;
        int row = f4 >> 5, c4 = f4 & 31;
        float4 va = *(const float4*)(xb + (size_t)(i0 + row) * C + c4 * 4);
        uint4 ta = make_uint4(to_tf32(va.x), to_tf32(va.y), to_tf32(va.z), to_tf32(va.w));
        *(uint4*)&As[row * AS_STRIDE + c4 * 4] = ta;
        float4 vb = *(const float4*)(xb + (size_t)(j0 + row) * C + c4 * 4);
        uint4 tb = make_uint4(to_tf32(vb.x), to_tf32(vb.y), to_tf32(vb.z), to_tf32(vb.w));
        *(uint4*)&Bs[row * AS_STRIDE + c4 * 4] = tb;
    }
    __syncthreads();

    {
        int r = tid & 127;
        const uint32_t* Row = ((tid < 128) ? As : Bs) + r * AS_STRIDE;
        float s = 0.0f;
        #pragma unroll
        for (int k = 0; k < 128; k += 4) {
            float4 v = *(const float4*)&Row[k];
            s = fmaf(v.x, v.x, s); s = fmaf(v.y, v.y, s);
            s = fmaf(v.z, v.z, s); s = fmaf(v.w, v.w, s);
        }
        sxx[tid] = s;
    }

    int warp_m = (wid >> 2) * 64;
    int warp_n = (wid & 3) * 32;

    float acc[4][4][4];
    #pragma unroll
    for (int e = 0; e < 4; ++e)
        #pragma unroll
        for (int f = 0; f < 4; ++f)
            #pragma unroll
            for (int q = 0; q < 4; ++q) acc[e][f][q] = 0.0f;

    int abase = (warp_m + grp) * AS_STRIDE + tg;
    int bbase = (warp_n + grp) * AS_STRIDE + tg;

    #pragma unroll 2
    for (int kb = 0; kb < 128; kb += 8) {
        uint32_t a[4][4], bf[4][2];
        #pragma unroll
        for (int e = 0; e < 4; ++e) {
            int r = abase + 16 * e * AS_STRIDE + kb;
            a[e][0] = As[r];
            a[e][1] = As[r + 8 * AS_STRIDE];
            a[e][2] = As[r + 4];
            a[e][3] = As[r + 8 * AS_STRIDE + 4];
        }
        #pragma unroll
        for (int f = 0; f < 4; ++f) {
            int r = bbase + 8 * f * AS_STRIDE + kb;
            bf[f][0] = Bs[r];
            bf[f][1] = Bs[r + 4];
        }
        #pragma unroll
        for (int e = 0; e < 4; ++e)
            #pragma unroll
            for (int f = 0; f < 4; ++f)
                mma_tf32(acc[e][f], a[e], bf[f]);
    }

    __syncthreads();

    float xi[4][2], xj[4][2];
    #pragma unroll
    for (int e = 0; e < 4; ++e) {
        int il = warp_m + 16 * e + grp;
        xi[e][0] = sxx[il];
        xi[e][1] = sxx[il + 8];
    }
    #pragma unroll
    for (int f = 0; f < 4; ++f) {
        int jl = warp_n + 8 * f + 2 * tg;
        xj[f][0] = sxx[128 + jl];
        xj[f][1] = sxx[128 + jl + 1];
    }

    __half* S = (__half*)sm;

    #pragma unroll
    for (int e = 0; e < 4; ++e) {
        int il = warp_m + 16 * e + grp;
        #pragma unroll
        for (int f = 0; f < 4; ++f) {
            int jl = warp_n + 8 * f + 2 * tg;
            float d00 = fmaf(-2.0f, acc[e][f][0], xi[e][0] + xj[f][0]);
            float d01 = fmaf(-2.0f, acc[e][f][1], xi[e][0] + xj[f][1]);
            float d10 = fmaf(-2.0f, acc[e][f][2], xi[e][1] + xj[f][0]);
            float d11 = fmaf(-2.0f, acc[e][f][3], xi[e][1] + xj[f][1]);
            float s00 = fsqrt_approx(fmaxf(d00, 0.0f));
            float s01 = fsqrt_approx(fmaxf(d01, 0.0f));
            float s10 = fsqrt_approx(fmaxf(d10, 0.0f));
            float s11 = fsqrt_approx(fmaxf(d11, 0.0f));
            *(__half2*)&S[il * HS_STRIDE + jl]       = __floats2half2_rn(s00, s01);
            *(__half2*)&S[(il + 8) * HS_STRIDE + jl] = __floats2half2_rn(s10, s11);
        }
    }
    __syncthreads();

    {
        long bbase2 = (long)b * LUP;
        #pragma unroll
        for (int q = tid; q < 128 * 128; q += 256) {
            int m = q >> 7, jj = q & 127;
            int i2 = i0 + m, j2 = j0 + jj;
            if (j2 > i2) {
                long ro = (long)i2 * (2 * T - 1 - i2) / 2 - i2 - 1;
                g_up[bbase2 + ro + j2] = S[m * HS_STRIDE + jj];
            }
        }
    }
}

// ---------------------------------------------------------------------------
// Kernel 2 (v6.1): conv with HMMA layers. Identical to R11 except L4 is a
// strided loop (384 outputs > 256 threads — the R11 correctness bug).
// ---------------------------------------------------------------------------
__global__ __launch_bounds__(256) void conv_kernel(
    const float* __restrict__ w0, const float* __restrict__ b0,
    const float* __restrict__ w1, const float* __restrict__ b1,
    const float* __restrict__ w2, const float* __restrict__ b2,
    const float* __restrict__ w3, const float* __restrict__ b3,
    const float* __restrict__ w4, const float* __restrict__ b4,
    const float* __restrict__ w5, const float* __restrict__ b5,
    const float* __restrict__ w6, const float* __restrict__ b6,
    const float* __restrict__ w7, const float* __restrict__ b7,
    float* __restrict__ out)
{
    __shared__ float  wgt[860];
    __shared__ __half BuH[1536];   // input distances
    __shared__ __half H0[6144];    // L0 out: 768 pos x 8ch
    __shared__ __half H1[3072];    // L1 out: 384 pos
    __shared__ __half H2[1536];    // L2 out: 192 pos
    __shared__ float  F3[768];     // L3 out: 96 pos (f32)
    __shared__ float  F4[384];     // L4 out: 48 pos
    __shared__ float  F5[192];     // L5 out: 24 pos
    __shared__ float  F6[96];      // L6 out: 12 pos

    int tid = threadIdx.x;
    int wid = tid >> 5;
    int lane = tid & 31;
    int c   = tid & 7;
    int b   = blockIdx.y;
    int blk = blockIdx.x;        // 0..340

    // ---- stage weights ----
    if (tid < 128) {
        wgt[ 24 + tid] = w1[tid];
        wgt[152 + tid] = w2[tid];
        wgt[280 + tid] = w3[tid];
        wgt[408 + tid] = w4[tid];
        wgt[536 + tid] = w5[tid];
        wgt[664 + tid] = w6[tid];
    } else {
        int u = tid - 128;
        if (u < 16)       wgt[u]            = w0[u];
        else if (u < 24)  wgt[u]            = b0[u - 16];
        else if (u < 32)  wgt[792 + (u-24)] = b1[u-24];
        else if (u < 40)  wgt[800 + (u-32)] = b2[u-32];
        else if (u < 48)  wgt[808 + (u-40)] = b3[u-40];
        else if (u < 56)  wgt[816 + (u-48)] = b4[u-48];
        else if (u < 64)  wgt[824 + (u-56)] = b5[u-56];
        else if (u < 72)  wgt[832 + (u-64)] = b6[u-64];
        else if (u < 88)  wgt[840 + (u-72)] = w7[u-72];
        else if (u == 88) wgt[856]          = b7[0];
    }

    // ---- load 1536 contiguous fp16 distances ----
    {
        const uint4* src = (const uint4*)(g_up + (size_t)b * LUP + (size_t)blk * 1536);
        uint4* dst = (uint4*)BuH;
        if (tid < 192) dst[tid] = src[tid];
    }
    __syncthreads();

    // ---- build register B-fragments + biases for layers 1..3 ----
    int g = lane >> 2, tq = lane & 3;
    uint32_t bf1[2], bf2[2], bf3[2];
    float bi1x, bi1y, bi2x, bi2y, bi3x, bi3y;
    {
        const float* W;
        W = wgt + 24;
        bf1[0] = pack_h2(W[g*16 + 4*tq],     W[g*16 + 4*tq + 2]);
        bf1[1] = pack_h2(W[g*16 + 4*tq + 1], W[g*16 + 4*tq + 3]);
        bi1x = wgt[792 + 2*tq]; bi1y = wgt[792 + 2*tq + 1];
        W = wgt + 152;
        bf2[0] = pack_h2(W[g*16 + 4*tq],     W[g*16 + 4*tq + 2]);
        bf2[1] = pack_h2(W[g*16 + 4*tq + 1], W[g*16 + 4*tq + 3]);
        bi2x = wgt[800 + 2*tq]; bi2y = wgt[800 + 2*tq + 1];
        W = wgt + 280;
        bf3[0] = pack_h2(W[g*16 + 4*tq],     W[g*16 + 4*tq + 2]);
        bf3[1] = pack_h2(W[g*16 + 4*tq + 1], W[g*16 + 4*tq + 3]);
        bi3x = wgt[808 + 2*tq]; bi3y = wgt[808 + 2*tq + 1];
    }

    // ---- L0: 1ch x 1536 -> 8ch x 768, fp16 out ----
    {
        float wa = wgt[2 * c], wb2 = wgt[2 * c + 1], bc = wgt[16 + c];
        const __half2* B2 = (const __half2*)BuH;
        #pragma unroll
        for (int it = 0; it < 24; ++it) {
            int q = it * 256 + tid;          // 0..6143; (q&7)==c, p=q>>3
            float2 u = __half22float2(B2[q >> 3]);
            float v = fmaf(wa, u.x, fmaf(wb2, u.y, bc));
            H0[q] = __float2half_rn(lrelu(v));
        }
    }
    __syncthreads();

    // ---- L1: H0 (768 pos) -> H1 (384 pos), 24 chunks of 16 ----
    #pragma unroll 1
    for (int ch = wid; ch < 24; ch += 8) {
        const char* base = (const char*)H0 + (ch * 16 + g) * 32 + tq * 4;
        uint32_t a[4];
        a[0] = *(const uint32_t*)(base);
        a[1] = *(const uint32_t*)(base + 256);
        a[2] = *(const uint32_t*)(base + 16);
        a[3] = *(const uint32_t*)(base + 272);
        float d[4] = {bi1x, bi1y, bi1x, bi1y};
        mma_f16(d, a, bf1);
        uint32_t h01 = pack_h2(lrelu(d[0]), lrelu(d[1]));
        uint32_t h23 = pack_h2(lrelu(d[2]), lrelu(d[3]));
        char* ob = (char*)H1 + (ch * 16 + g) * 16 + tq * 4;
        *(uint32_t*)ob = h01;
        *(uint32_t*)(ob + 128) = h23;
    }
    __syncthreads();

    // ---- L2: H1 (384 pos) -> H2 (192 pos), 12 chunks ----
    #pragma unroll 1
    for (int ch = wid; ch < 12; ch += 8) {
        const char* base = (const char*)H1 + (ch * 16 + g) * 32 + tq * 4;
        uint32_t a[4];
        a[0] = *(const uint32_t*)(base);
        a[1] = *(const uint32_t*)(base + 256);
        a[2] = *(const uint32_t*)(base + 16);
        a[3] = *(const uint32_t*)(base + 272);
        float d[4] = {bi2x, bi2y, bi2x, bi2y};
        mma_f16(d, a, bf2);
        uint32_t h01 = pack_h2(lrelu(d[0]), lrelu(d[1]));
        uint32_t h23 = pack_h2(lrelu(d[2]), lrelu(d[3]));
        char* ob = (char*)H2 + (ch * 16 + g) * 16 + tq * 4;
        *(uint32_t*)ob = h01;
        *(uint32_t*)(ob + 128) = h23;
    }
    __syncthreads();

    // ---- L3: H2 (192 pos) -> F3 (96 pos, f32 out), 6 chunks ----
    if (wid < 6) {
        int ch = wid;
        const char* base = (const char*)H2 + (ch * 16 + g) * 32 + tq * 4;
        uint32_t a[4];
        a[0] = *(const uint32_t*)(base);
        a[1] = *(const uint32_t*)(base + 256);
        a[2] = *(const uint32_t*)(base + 16);
        a[3] = *(const uint32_t*)(base + 272);
        float d[4] = {bi3x, bi3y, bi3x, bi3y};
        mma_f16(d, a, bf3);
        float* ob = F3 + (ch * 16 + g) * 8 + 2 * tq;
        ob[0]  = lrelu(d[0]);  ob[1]      = lrelu(d[1]);
        ob[64] = lrelu(d[2]);  ob[64 + 1] = lrelu(d[3]);
    }
    __syncthreads();

    // ---- tail f32 scalar layers ----
    // L4: F3 (96 pos) -> F4 (48 pos): 384 outputs, strided over 256 threads
    for (int q = tid; q < 384; q += 256) {
        int p = q >> 3;
        int cc = q & 7;
        const float4* s4 = (const float4*)(F3 + 16 * p);
        const float4* Wc = (const float4*)(wgt + 408 + cc * 16);
        float4 wrA = Wc[0], wrB = Wc[1], wrC = Wc[2], wrD = Wc[3];
        float4 a0 = s4[0], a1 = s4[1], a2 = s4[2], a3 = s4[3];
        float acc = wgt[816 + cc];
        acc = fmaf(wrA.x, a0.x, acc); acc = fmaf(wrA.y, a2.x, acc);
        acc = fmaf(wrA.z, a0.y, acc); acc = fmaf(wrA.w, a2.y, acc);
        acc = fmaf(wrB.x, a0.z, acc); acc = fmaf(wrB.y, a2.z, acc);
        acc = fmaf(wrB.z, a0.w, acc); acc = fmaf(wrB.w, a2.w, acc);
        acc = fmaf(wrC.x, a1.x, acc); acc = fmaf(wrC.y, a3.x, acc);
        acc = fmaf(wrC.z, a1.y, acc); acc = fmaf(wrC.w, a3.y, acc);
        acc = fmaf(wrD.x, a1.z, acc); acc = fmaf(wrD.y, a3.z, acc);
        acc = fmaf(wrD.z, a1.w, acc); acc = fmaf(wrD.w, a3.w, acc);
        F4[p * 8 + cc] = lrelu(acc);
    }
    __syncthreads();
    // L5: F4 (48) -> F5 (24): 192 outputs
    if (tid < 192) {
        int p = tid >> 3;
        const float4* s4 = (const float4*)(F4 + 16 * p);
        const float4* Wc = (const float4*)(wgt + 536 + c * 16);
        float4 wrA = Wc[0], wrB = Wc[1], wrC = Wc[2], wrD = Wc[3];
        float4 a0 = s4[0], a1 = s4[1], a2 = s4[2], a3 = s4[3];
        float acc = wgt[824 + c];
        acc = fmaf(wrA.x, a0.x, acc); acc = fmaf(wrA.y, a2.x, acc);
        acc = fmaf(wrA.z, a0.y, acc); acc = fmaf(wrA.w, a2.y, acc);
        acc = fmaf(wrB.x, a0.z, acc); acc = fmaf(wrB.y, a2.z, acc);
        acc = fmaf(wrB.z, a0.w, acc); acc = fmaf(wrB.w, a2.w, acc);
        acc = fmaf(wrC.x, a1.x, acc); acc = fmaf(wrC.y, a3.x, acc);
        acc = fmaf(wrC.z, a1.y, acc); acc = fmaf(wrC.w, a3.y, acc);
        acc = fmaf(wrD.x, a1.z, acc); acc = fmaf(wrD.y, a3.z, acc);
        acc = fmaf(wrD.z, a1.w, acc); acc = fmaf(wrD.w, a3.w, acc);
        F5[p * 8 + c] = lrelu(acc);
    }
    __syncthreads();
    // L6: F5 (24) -> F6 (12): 96 outputs
    if (tid < 96) {
        int p = tid >> 3;
        const float4* s4 = (const float4*)(F5 + 16 * p);
        const float4* Wc = (const float4*)(wgt + 664 + c * 16);
        float4 wrA = Wc[0], wrB = Wc[1], wrC = Wc[2], wrD = Wc[3];
        float4 a0 = s4[0], a1 = s4[1], a2 = s4[2], a3 = s4[3];
        float acc = wgt[832 + c];
        acc = fmaf(wrA.x, a0.x, acc); acc = fmaf(wrA.y, a2.x, acc);
        acc = fmaf(wrA.z, a0.y, acc); acc = fmaf(wrA.w, a2.y, acc);
        acc = fmaf(wrB.x, a0.z, acc); acc = fmaf(wrB.y, a2.z, acc);
        acc = fmaf(wrB.z, a0.w, acc); acc = fmaf(wrB.w, a2.w, acc);
        acc = fmaf(wrC.x, a1.x, acc); acc = fmaf(wrC.y, a3.x, acc);
        acc = fmaf(wrC.z, a1.y, acc); acc = fmaf(wrC.w, a3.y, acc);
        acc = fmaf(wrD.x, a1.z, acc); acc = fmaf(wrD.y, a3.z, acc);
        acc = fmaf(wrD.z, a1.w, acc); acc = fmaf(wrD.w, a3.w, acc);
        F6[p * 8 + c] = lrelu(acc);
    }
    __syncthreads();
    // L7: F6 (12) -> out (6, no activation)
    if (tid < 6) {
        const float* s0 = F6 + 16 * tid;
        const float4* Wc = (const float4*)(wgt + 840);
        float4 wa = Wc[0], wb = Wc[1], wc2 = Wc[2], wd = Wc[3];
        float acc = wgt[856];
        acc = fmaf(wa.x,  s0[0], acc); acc = fmaf(wa.y,  s0[8],  acc);
        acc = fmaf(wa.z,  s0[1], acc); acc = fmaf(wa.w,  s0[9],  acc);
        acc = fmaf(wb.x,  s0[2], acc); acc = fmaf(wb.y,  s0[10], acc);
        acc = fmaf(wb.z,  s0[3], acc); acc = fmaf(wb.w,  s0[11], acc);
        acc = fmaf(wc2.x, s0[4], acc); acc = fmaf(wc2.y, s0[12], acc);
        acc = fmaf(wc2.z, s0[5], acc); acc = fmaf(wc2.w, s0[13], acc);
        acc = fmaf(wd.x,  s0[6], acc); acc = fmaf(wd.y,  s0[14], acc);
        acc = fmaf(wd.z,  s0[7], acc); acc = fmaf(wd.w,  s0[15], acc);
        out[b * NOUT + blk * 6 + tid] = acc;
    }
}

// ---------------------------------------------------------------------------
extern "C" void kernel_launch(void* const* d_in, const int* in_sizes, int n_in,
                              void* d_out, int out_size) {
    const float* x = (const float*)d_in[0];
    const float* w[8];
    const float* bb[8];
    for (int i = 0; i < 8; ++i) {
        w[i]  = (const float*)d_in[1 + 2 * i];
        bb[i] = (const float*)d_in[2 + 2 * i];
    }
    float* out = (float*)d_out;

    cudaFuncSetAttribute(dist_kernel,
                         cudaFuncAttributeMaxDynamicSharedMemorySize, DIST_SMEM);

    dist_kernel<<<dim3(36, NB), 256, DIST_SMEM>>>(x);
    conv_kernel<<<dim3(341, NB), 256>>>(
        w[0], bb[0], w[1], bb[1], w[2], bb[2], w[3], bb[3],
        w[4], bb[4], w[5], bb[5], w[6], bb[6], w[7], bb[7], out);
}

// round 13
// speedup vs baseline: 1.7754x; 1.0825x over previous
#include <cuda_runtime.h>
#include <cuda_fp16.h>
#include <math.h>
#include <stdint.h>

#define T 1024
#define C 128
#define NB 16
#define LUP 523776          // T*(T-1)/2
#define NOUT 2046           // LUP / 256
#define LEAK 0.2f

// ---------------------------------------------------------------------------
// Device globals (scratch)
// ---------------------------------------------------------------------------
__device__ __half g_up[(size_t)NB * LUP];  // packed upper-triangle distances (fp16)

// ---------------------------------------------------------------------------
// Helpers
// ---------------------------------------------------------------------------
__device__ __forceinline__ uint32_t to_tf32(float f) {
    uint32_t r;
    asm("cvt.rna.tf32.f32 %0, %1;" : "=r"(r) : "f"(f));
    return r;
}

__device__ __forceinline__ void mma_tf32(float* d, const uint32_t* a, const uint32_t* b) {
    asm volatile(
        "mma.sync.aligned.m16n8k8.row.col.f32.tf32.tf32.f32 "
        "{%0,%1,%2,%3}, {%4,%5,%6,%7}, {%8,%9}, {%0,%1,%2,%3};"
        : "+f"(d[0]), "+f"(d[1]), "+f"(d[2]), "+f"(d[3])
        : "r"(a[0]), "r"(a[1]), "r"(a[2]), "r"(a[3]),
          "r"(b[0]), "r"(b[1]));
}

__device__ __forceinline__ void mma_f16(float* d, const uint32_t* a, const uint32_t* b) {
    asm volatile(
        "mma.sync.aligned.m16n8k16.row.col.f32.f16.f16.f32 "
        "{%0,%1,%2,%3}, {%4,%5,%6,%7}, {%8,%9}, {%0,%1,%2,%3};"
        : "+f"(d[0]), "+f"(d[1]), "+f"(d[2]), "+f"(d[3])
        : "r"(a[0]), "r"(a[1]), "r"(a[2]), "r"(a[3]),
          "r"(b[0]), "r"(b[1]));
}

__device__ __forceinline__ float lrelu(float v) {
    return fmaxf(v, LEAK * v);
}

__device__ __forceinline__ float fsqrt_approx(float v) {
    float r;
    asm("sqrt.approx.f32 %0, %1;" : "=f"(r) : "f"(v));
    return r;
}

__device__ __forceinline__ uint32_t pack_h2(float x, float y) {
    __half2 h = __floats2half2_rn(x, y);
    return *(uint32_t*)&h;
}

// ---------------------------------------------------------------------------
// Kernel 1: tf32 mma.sync Gram tiles -> packed fp16 sqrt distances.
// (verbatim from round-10/12 passing builds; xx fused in-block)
// ---------------------------------------------------------------------------
#define AS_STRIDE 132
#define AS_BYTES  (128 * AS_STRIDE * 4)       // 67584
#define DIST_SMEM (2 * AS_BYTES + 1024)       // + sxx[256]
#define HS_STRIDE 130

__global__ __launch_bounds__(256) void dist_kernel(const float* __restrict__ x) {
    extern __shared__ __align__(16) unsigned char sm[];
    uint32_t* As = (uint32_t*)sm;
    uint32_t* Bs = (uint32_t*)(sm + AS_BYTES);
    float* sxx   = (float*)(sm + 2 * AS_BYTES);

    int tid = threadIdx.x;
    int wid = tid >> 5;
    int lane = tid & 31;
    int grp = lane >> 2;
    int tg  = lane & 3;

    int b = blockIdx.y;
    int t = blockIdx.x;
    int ti = 0, rem = t;
    while (rem >= 8 - ti) { rem -= 8 - ti; ++ti; }
    int tj = ti + rem;
    int i0 = ti * 128, j0 = tj * 128;

    const float* xb = x + (size_t)b * T * C;

    #pragma unroll
    for (int it = 0; it < 16; ++it) {
        int f4 = it * 256 + tid;
        int row = f4 >> 5, c4 = f4 & 31;
        float4 va = *(const float4*)(xb + (size_t)(i0 + row) * C + c4 * 4);
        uint4 ta = make_uint4(to_tf32(va.x), to_tf32(va.y), to_tf32(va.z), to_tf32(va.w));
        *(uint4*)&As[row * AS_STRIDE + c4 * 4] = ta;
        float4 vb = *(const float4*)(xb + (size_t)(j0 + row) * C + c4 * 4);
        uint4 tb = make_uint4(to_tf32(vb.x), to_tf32(vb.y), to_tf32(vb.z), to_tf32(vb.w));
        *(uint4*)&Bs[row * AS_STRIDE + c4 * 4] = tb;
    }
    __syncthreads();

    {
        int r = tid & 127;
        const uint32_t* Row = ((tid < 128) ? As : Bs) + r * AS_STRIDE;
        float s = 0.0f;
        #pragma unroll
        for (int k = 0; k < 128; k += 4) {
            float4 v = *(const float4*)&Row[k];
            s = fmaf(v.x, v.x, s); s = fmaf(v.y, v.y, s);
            s = fmaf(v.z, v.z, s); s = fmaf(v.w, v.w, s);
        }
        sxx[tid] = s;
    }

    int warp_m = (wid >> 2) * 64;
    int warp_n = (wid & 3) * 32;

    float acc[4][4][4];
    #pragma unroll
    for (int e = 0; e < 4; ++e)
        #pragma unroll
        for (int f = 0; f < 4; ++f)
            #pragma unroll
            for (int q = 0; q < 4; ++q) acc[e][f][q] = 0.0f;

    int abase = (warp_m + grp) * AS_STRIDE + tg;
    int bbase = (warp_n + grp) * AS_STRIDE + tg;

    #pragma unroll 2
    for (int kb = 0; kb < 128; kb += 8) {
        uint32_t a[4][4], bf[4][2];
        #pragma unroll
        for (int e = 0; e < 4; ++e) {
            int r = abase + 16 * e * AS_STRIDE + kb;
            a[e][0] = As[r];
            a[e][1] = As[r + 8 * AS_STRIDE];
            a[e][2] = As[r + 4];
            a[e][3] = As[r + 8 * AS_STRIDE + 4];
        }
        #pragma unroll
        for (int f = 0; f < 4; ++f) {
            int r = bbase + 8 * f * AS_STRIDE + kb;
            bf[f][0] = Bs[r];
            bf[f][1] = Bs[r + 4];
        }
        #pragma unroll
        for (int e = 0; e < 4; ++e)
            #pragma unroll
            for (int f = 0; f < 4; ++f)
                mma_tf32(acc[e][f], a[e], bf[f]);
    }

    __syncthreads();

    float xi[4][2], xj[4][2];
    #pragma unroll
    for (int e = 0; e < 4; ++e) {
        int il = warp_m + 16 * e + grp;
        xi[e][0] = sxx[il];
        xi[e][1] = sxx[il + 8];
    }
    #pragma unroll
    for (int f = 0; f < 4; ++f) {
        int jl = warp_n + 8 * f + 2 * tg;
        xj[f][0] = sxx[128 + jl];
        xj[f][1] = sxx[128 + jl + 1];
    }

    __half* S = (__half*)sm;

    #pragma unroll
    for (int e = 0; e < 4; ++e) {
        int il = warp_m + 16 * e + grp;
        #pragma unroll
        for (int f = 0; f < 4; ++f) {
            int jl = warp_n + 8 * f + 2 * tg;
            float d00 = fmaf(-2.0f, acc[e][f][0], xi[e][0] + xj[f][0]);
            float d01 = fmaf(-2.0f, acc[e][f][1], xi[e][0] + xj[f][1]);
            float d10 = fmaf(-2.0f, acc[e][f][2], xi[e][1] + xj[f][0]);
            float d11 = fmaf(-2.0f, acc[e][f][3], xi[e][1] + xj[f][1]);
            float s00 = fsqrt_approx(fmaxf(d00, 0.0f));
            float s01 = fsqrt_approx(fmaxf(d01, 0.0f));
            float s10 = fsqrt_approx(fmaxf(d10, 0.0f));
            float s11 = fsqrt_approx(fmaxf(d11, 0.0f));
            *(__half2*)&S[il * HS_STRIDE + jl]       = __floats2half2_rn(s00, s01);
            *(__half2*)&S[(il + 8) * HS_STRIDE + jl] = __floats2half2_rn(s10, s11);
        }
    }
    __syncthreads();

    {
        long bbase2 = (long)b * LUP;
        #pragma unroll
        for (int q = tid; q < 128 * 128; q += 256) {
            int m = q >> 7, jj = q & 127;
            int i2 = i0 + m, j2 = j0 + jj;
            if (j2 > i2) {
                long ro = (long)i2 * (2 * T - 1 - i2) / 2 - i2 - 1;
                g_up[bbase2 + ro + j2] = S[m * HS_STRIDE + jj];
            }
        }
    }
}

// ---------------------------------------------------------------------------
// Kernel 2 (v6.2): HMMA conv. Identical to R12 except L0:
//  - one thread per L0 POSITION (768 = 3*256): LDG half2 pair straight from
//    g_up (no BuH staging, one barrier fewer), 8 channels in f32 with
//    register weights, one STS.128 per position (conflict-free).
//  - L0 mem-instructions per warp: 48 -> 6.
// ---------------------------------------------------------------------------
__global__ __launch_bounds__(256) void conv_kernel(
    const float* __restrict__ w0, const float* __restrict__ b0,
    const float* __restrict__ w1, const float* __restrict__ b1,
    const float* __restrict__ w2, const float* __restrict__ b2,
    const float* __restrict__ w3, const float* __restrict__ b3,
    const float* __restrict__ w4, const float* __restrict__ b4,
    const float* __restrict__ w5, const float* __restrict__ b5,
    const float* __restrict__ w6, const float* __restrict__ b6,
    const float* __restrict__ w7, const float* __restrict__ b7,
    float* __restrict__ out)
{
    __shared__ float  wgt[860];
    __shared__ __align__(16) __half H0[6144];    // L0 out: 768 pos x 8ch
    __shared__ __align__(16) __half H1[3072];    // L1 out: 384 pos
    __shared__ __align__(16) __half H2[1536];    // L2 out: 192 pos
    __shared__ float  F3[768];     // L3 out: 96 pos (f32)
    __shared__ float  F4[384];     // L4 out: 48 pos
    __shared__ float  F5[192];     // L5 out: 24 pos
    __shared__ float  F6[96];      // L6 out: 12 pos

    int tid = threadIdx.x;
    int wid = tid >> 5;
    int lane = tid & 31;
    int c   = tid & 7;
    int b   = blockIdx.y;
    int blk = blockIdx.x;        // 0..340

    // ---- stage weights ----
    if (tid < 128) {
        wgt[ 24 + tid] = w1[tid];
        wgt[152 + tid] = w2[tid];
        wgt[280 + tid] = w3[tid];
        wgt[408 + tid] = w4[tid];
        wgt[536 + tid] = w5[tid];
        wgt[664 + tid] = w6[tid];
    } else {
        int u = tid - 128;
        if (u < 16)       wgt[u]            = w0[u];
        else if (u < 24)  wgt[u]            = b0[u - 16];
        else if (u < 32)  wgt[792 + (u-24)] = b1[u-24];
        else if (u < 40)  wgt[800 + (u-32)] = b2[u-32];
        else if (u < 48)  wgt[808 + (u-40)] = b3[u-40];
        else if (u < 56)  wgt[816 + (u-48)] = b4[u-48];
        else if (u < 64)  wgt[824 + (u-56)] = b5[u-56];
        else if (u < 72)  wgt[832 + (u-64)] = b6[u-64];
        else if (u < 88)  wgt[840 + (u-72)] = w7[u-72];
        else if (u == 88) wgt[856]          = b7[0];
    }
    __syncthreads();

    // ---- build register B-fragments + biases for layers 1..3 ----
    int g = lane >> 2, tq = lane & 3;
    uint32_t bf1[2], bf2[2], bf3[2];
    float bi1x, bi1y, bi2x, bi2y, bi3x, bi3y;
    {
        const float* W;
        W = wgt + 24;
        bf1[0] = pack_h2(W[g*16 + 4*tq],     W[g*16 + 4*tq + 2]);
        bf1[1] = pack_h2(W[g*16 + 4*tq + 1], W[g*16 + 4*tq + 3]);
        bi1x = wgt[792 + 2*tq]; bi1y = wgt[792 + 2*tq + 1];
        W = wgt + 152;
        bf2[0] = pack_h2(W[g*16 + 4*tq],     W[g*16 + 4*tq + 2]);
        bf2[1] = pack_h2(W[g*16 + 4*tq + 1], W[g*16 + 4*tq + 3]);
        bi2x = wgt[800 + 2*tq]; bi2y = wgt[800 + 2*tq + 1];
        W = wgt + 280;
        bf3[0] = pack_h2(W[g*16 + 4*tq],     W[g*16 + 4*tq + 2]);
        bf3[1] = pack_h2(W[g*16 + 4*tq + 1], W[g*16 + 4*tq + 3]);
        bi3x = wgt[808 + 2*tq]; bi3y = wgt[808 + 2*tq + 1];
    }

    // ---- L0: one thread per position, LDG direct from g_up, STS.128 out ----
    {
        // hoist L0 weights to registers
        float w0r[16], b0r[8];
        #pragma unroll
        for (int k = 0; k < 16; ++k) w0r[k] = wgt[k];
        #pragma unroll
        for (int k = 0; k < 8; ++k)  b0r[k] = wgt[16 + k];

        const __half2* gin = (const __half2*)(g_up + (size_t)b * LUP + (size_t)blk * 1536);
        #pragma unroll
        for (int it = 0; it < 3; ++it) {
            int p = it * 256 + tid;              // 0..767
            float2 u = __half22float2(gin[p]);   // inputs 2p, 2p+1
            float o[8];
            #pragma unroll
            for (int cc = 0; cc < 8; ++cc)
                o[cc] = lrelu(fmaf(w0r[2*cc], u.x, fmaf(w0r[2*cc + 1], u.y, b0r[cc])));
            uint4 pk = make_uint4(pack_h2(o[0], o[1]), pack_h2(o[2], o[3]),
                                  pack_h2(o[4], o[5]), pack_h2(o[6], o[7]));
            *(uint4*)((char*)H0 + p * 16) = pk;
        }
    }
    __syncthreads();

    // ---- L1: H0 (768 pos) -> H1 (384 pos), 24 chunks of 16 ----
    #pragma unroll 1
    for (int ch = wid; ch < 24; ch += 8) {
        const char* base = (const char*)H0 + (ch * 16 + g) * 32 + tq * 4;
        uint32_t a[4];
        a[0] = *(const uint32_t*)(base);
        a[1] = *(const uint32_t*)(base + 256);
        a[2] = *(const uint32_t*)(base + 16);
        a[3] = *(const uint32_t*)(base + 272);
        float d[4] = {bi1x, bi1y, bi1x, bi1y};
        mma_f16(d, a, bf1);
        uint32_t h01 = pack_h2(lrelu(d[0]), lrelu(d[1]));
        uint32_t h23 = pack_h2(lrelu(d[2]), lrelu(d[3]));
        char* ob = (char*)H1 + (ch * 16 + g) * 16 + tq * 4;
        *(uint32_t*)ob = h01;
        *(uint32_t*)(ob + 128) = h23;
    }
    __syncthreads();

    // ---- L2: H1 (384 pos) -> H2 (192 pos), 12 chunks ----
    #pragma unroll 1
    for (int ch = wid; ch < 12; ch += 8) {
        const char* base = (const char*)H1 + (ch * 16 + g) * 32 + tq * 4;
        uint32_t a[4];
        a[0] = *(const uint32_t*)(base);
        a[1] = *(const uint32_t*)(base + 256);
        a[2] = *(const uint32_t*)(base + 16);
        a[3] = *(const uint32_t*)(base + 272);
        float d[4] = {bi2x, bi2y, bi2x, bi2y};
        mma_f16(d, a, bf2);
        uint32_t h01 = pack_h2(lrelu(d[0]), lrelu(d[1]));
        uint32_t h23 = pack_h2(lrelu(d[2]), lrelu(d[3]));
        char* ob = (char*)H2 + (ch * 16 + g) * 16 + tq * 4;
        *(uint32_t*)ob = h01;
        *(uint32_t*)(ob + 128) = h23;
    }
    __syncthreads();

    // ---- L3: H2 (192 pos) -> F3 (96 pos, f32 out), 6 chunks ----
    if (wid < 6) {
        int ch = wid;
        const char* base = (const char*)H2 + (ch * 16 + g) * 32 + tq * 4;
        uint32_t a[4];
        a[0] = *(const uint32_t*)(base);
        a[1] = *(const uint32_t*)(base + 256);
        a[2] = *(const uint32_t*)(base + 16);
        a[3] = *(const uint32_t*)(base + 272);
        float d[4] = {bi3x, bi3y, bi3x, bi3y};
        mma_f16(d, a, bf3);
        float* ob = F3 + (ch * 16 + g) * 8 + 2 * tq;
        ob[0]  = lrelu(d[0]);  ob[1]      = lrelu(d[1]);
        ob[64] = lrelu(d[2]);  ob[64 + 1] = lrelu(d[3]);
    }
    __syncthreads();

    // ---- tail f32 scalar layers ----
    // L4: F3 (96 pos) -> F4 (48 pos): 384 outputs, strided
    for (int q = tid; q < 384; q += 256) {
        int p = q >> 3;
        int cc = q & 7;
        const float4* s4 = (const float4*)(F3 + 16 * p);
        const float4* Wc = (const float4*)(wgt + 408 + cc * 16);
        float4 wrA = Wc[0], wrB = Wc[1], wrC = Wc[2], wrD = Wc[3];
        float4 a0 = s4[0], a1 = s4[1], a2 = s4[2], a3 = s4[3];
        float acc = wgt[816 + cc];
        acc = fmaf(wrA.x, a0.x, acc); acc = fmaf(wrA.y, a2.x, acc);
        acc = fmaf(wrA.z, a0.y, acc); acc = fmaf(wrA.w, a2.y, acc);
        acc = fmaf(wrB.x, a0.z, acc); acc = fmaf(wrB.y, a2.z, acc);
        acc = fmaf(wrB.z, a0.w, acc); acc = fmaf(wrB.w, a2.w, acc);
        acc = fmaf(wrC.x, a1.x, acc); acc = fmaf(wrC.y, a3.x, acc);
        acc = fmaf(wrC.z, a1.y, acc); acc = fmaf(wrC.w, a3.y, acc);
        acc = fmaf(wrD.x, a1.z, acc); acc = fmaf(wrD.y, a3.z, acc);
        acc = fmaf(wrD.z, a1.w, acc); acc = fmaf(wrD.w, a3.w, acc);
        F4[p * 8 + cc] = lrelu(acc);
    }
    __syncthreads();
    // L5: F4 (48) -> F5 (24): 192 outputs
    if (tid < 192) {
        int p = tid >> 3;
        const float4* s4 = (const float4*)(F4 + 16 * p);
        const float4* Wc = (const float4*)(wgt + 536 + c * 16);
        float4 wrA = Wc[0], wrB = Wc[1], wrC = Wc[2], wrD = Wc[3];
        float4 a0 = s4[0], a1 = s4[1], a2 = s4[2], a3 = s4[3];
        float acc = wgt[824 + c];
        acc = fmaf(wrA.x, a0.x, acc); acc = fmaf(wrA.y, a2.x, acc);
        acc = fmaf(wrA.z, a0.y, acc); acc = fmaf(wrA.w, a2.y, acc);
        acc = fmaf(wrB.x, a0.z, acc); acc = fmaf(wrB.y, a2.z, acc);
        acc = fmaf(wrB.z, a0.w, acc); acc = fmaf(wrB.w, a2.w, acc);
        acc = fmaf(wrC.x, a1.x, acc); acc = fmaf(wrC.y, a3.x, acc);
        acc = fmaf(wrC.z, a1.y, acc); acc = fmaf(wrC.w, a3.y, acc);
        acc = fmaf(wrD.x, a1.z, acc); acc = fmaf(wrD.y, a3.z, acc);
        acc = fmaf(wrD.z, a1.w, acc); acc = fmaf(wrD.w, a3.w, acc);
        F5[p * 8 + c] = lrelu(acc);
    }
    __syncthreads();
    // L6: F5 (24) -> F6 (12): 96 outputs
    if (tid < 96) {
        int p = tid >> 3;
        const float4* s4 = (const float4*)(F5 + 16 * p);
        const float4* Wc = (const float4*)(wgt + 664 + c * 16);
        float4 wrA = Wc[0], wrB = Wc[1], wrC = Wc[2], wrD = Wc[3];
        float4 a0 = s4[0], a1 = s4[1], a2 = s4[2], a3 = s4[3];
        float acc = wgt[832 + c];
        acc = fmaf(wrA.x, a0.x, acc); acc = fmaf(wrA.y, a2.x, acc);
        acc = fmaf(wrA.z, a0.y, acc); acc = fmaf(wrA.w, a2.y, acc);
        acc = fmaf(wrB.x, a0.z, acc); acc = fmaf(wrB.y, a2.z, acc);
        acc = fmaf(wrB.z, a0.w, acc); acc = fmaf(wrB.w, a2.w, acc);
        acc = fmaf(wrC.x, a1.x, acc); acc = fmaf(wrC.y, a3.x, acc);
        acc = fmaf(wrC.z, a1.y, acc); acc = fmaf(wrC.w, a3.y, acc);
        acc = fmaf(wrD.x, a1.z, acc); acc = fmaf(wrD.y, a3.z, acc);
        acc = fmaf(wrD.z, a1.w, acc); acc = fmaf(wrD.w, a3.w, acc);
        F6[p * 8 + c] = lrelu(acc);
    }
    __syncthreads();
    // L7: F6 (12) -> out (6, no activation)
    if (tid < 6) {
        const float* s0 = F6 + 16 * tid;
        const float4* Wc = (const float4*)(wgt + 840);
        float4 wa = Wc[0], wb = Wc[1], wc2 = Wc[2], wd = Wc[3];
        float acc = wgt[856];
        acc = fmaf(wa.x,  s0[0], acc); acc = fmaf(wa.y,  s0[8],  acc);
        acc = fmaf(wa.z,  s0[1], acc); acc = fmaf(wa.w,  s0[9],  acc);
        acc = fmaf(wb.x,  s0[2], acc); acc = fmaf(wb.y,  s0[10], acc);
        acc = fmaf(wb.z,  s0[3], acc); acc = fmaf(wb.w,  s0[11], acc);
        acc = fmaf(wc2.x, s0[4], acc); acc = fmaf(wc2.y, s0[12], acc);
        acc = fmaf(wc2.z, s0[5], acc); acc = fmaf(wc2.w, s0[13], acc);
        acc = fmaf(wd.x,  s0[6], acc); acc = fmaf(wd.y,  s0[14], acc);
        acc = fmaf(wd.z,  s0[7], acc); acc = fmaf(wd.w,  s0[15], acc);
        out[b * NOUT + blk * 6 + tid] = acc;
    }
}

// ---------------------------------------------------------------------------
extern "C" void kernel_launch(void* const* d_in, const int* in_sizes, int n_in,
                              void* d_out, int out_size) {
    const float* x = (const float*)d_in[0];
    const float* w[8];
    const float* bb[8];
    for (int i = 0; i < 8; ++i) {
        w[i]  = (const float*)d_in[1 + 2 * i];
        bb[i] = (const float*)d_in[2 + 2 * i];
    }
    float* out = (float*)d_out;

    cudaFuncSetAttribute(dist_kernel,
                         cudaFuncAttributeMaxDynamicSharedMemorySize, DIST_SMEM);

    dist_kernel<<<dim3(36, NB), 256, DIST_SMEM>>>(x);
    conv_kernel<<<dim3(341, NB), 256>>>(
        w[0], bb[0], w[1], bb[1], w[2], bb[2], w[3], bb[3],
        w[4], bb[4], w[5], bb[5], w[6], bb[6], w[7], bb[7], out);
}